// round 16
// baseline (speedup 1.0000x reference)
#include <cuda_runtime.h>
#include <cuda_bf16.h>
#include <math.h>
#include <stdint.h>

// ---------------- problem constants ----------------
#define NN      50000
#define NPREV   50000
#define NFEATS  256
#define NHID    256
#define NHEADS  4
#define HD      64
#define DEG_IN  16
#define DEG_C   8
#define ALPHA   0.2f

// ---------------- device scratch ----------------
__device__ float d_Wh  [NN * NHID];
__device__ float d_x   [NN * NHID];
__device__ float d_Whp [NPREV * NHID];
__device__ float d_h   [NN * NHID];
__device__ float d_hr  [NN * NHID];
__device__ float d_grz [NN * 512];
__device__ float d_gin [NN * NHID];
__device__ float d_ghn [NN * NHID];
__device__ float d_pk_intra[NHID * NFEATS];
__device__ float d_pk_cross[NHID * NHID];
__device__ float d_pih[768 * 256];
__device__ float d_phh[768 * 256];
__device__ float d_vmat[NFEATS * NHEADS];
__device__ float d_es [NN * NHEADS];
__device__ float d_ed [NN * NHEADS];
__device__ float d_esP[NPREV * NHEADS];
__device__ float d_edX[NN * NHEADS];

// ---------------- helpers ----------------
__device__ __forceinline__ uint32_t smem_u32(const void* p) {
    uint32_t a;
    asm("{ .reg .u64 t; cvta.to.shared.u64 t, %1; cvt.u32.u64 %0, t; }" : "=r"(a) : "l"(p));
    return a;
}
__device__ __forceinline__ uint32_t f2tf32(float x) {
    uint32_t r;
    asm("cvt.rna.tf32.f32 %0, %1;" : "=r"(r) : "f"(x));
    return r;
}
__device__ __forceinline__ void cp16(uint32_t dst, const void* src) {
    asm volatile("cp.async.cg.shared.global [%0], [%1], 16;" :: "r"(dst), "l"(src));
}
__device__ __forceinline__ void cp_commit() {
    asm volatile("cp.async.commit_group;" ::: "memory");
}
template<int N>
__device__ __forceinline__ void cp_wait() {
    asm volatile("cp.async.wait_group %0;" :: "n"(N) : "memory");
}
__device__ __forceinline__ void mma_tf32(float* d, const uint32_t* a, const uint32_t* b) {
    asm volatile(
        "mma.sync.aligned.m16n8k8.row.col.f32.tf32.tf32.f32 "
        "{%0,%1,%2,%3},{%4,%5,%6,%7},{%8,%9},{%0,%1,%2,%3};"
        : "+f"(d[0]), "+f"(d[1]), "+f"(d[2]), "+f"(d[3])
        : "r"(a[0]), "r"(a[1]), "r"(a[2]), "r"(a[3]), "r"(b[0]), "r"(b[1]));
}
__device__ __forceinline__ float fsig(float x) {
    return 1.f / (1.f + __expf(-x));
}
__device__ __forceinline__ float ftanh(float x) {
    float e = __expf(2.f * x);
    return 1.f - 2.f / (e + 1.f);
}

#define BMM 128
#define LDPA 36
#define LDPB 40
#define PLANE_A  (128 * LDPA * 4)
#define PLANE_BB (128 * LDPB * 4)
#define STAGE_SZ (PLANE_A + PLANE_BB)
#define SMEMSZ   (2 * STAGE_SZ)

#define STAGE_CHUNK(Aptr, Bptr, koff, buf)                                        \
do {                                                                              \
    uint32_t abase = sb + (buf) * STAGE_SZ;                                       \
    uint32_t bbase = abase + PLANE_A;                                             \
    _Pragma("unroll")                                                             \
    for (int j = 0; j < 4; j++) {                                                 \
        int r = (tid >> 3) + j * 32;                                              \
        int row = m0 + r; if (row >= M) row = M - 1;                              \
        cp16(abase + r * (LDPA * 4) + (tid & 7) * 16,                             \
             &(Aptr)[(size_t)row * 256 + (koff) + (tid & 7) * 4]);                \
    }                                                                             \
    _Pragma("unroll")                                                             \
    for (int j = 0; j < 4; j++) {                                                 \
        int r = (tid >> 3) + j * 32;                                              \
        cp16(bbase + r * (LDPB * 4) + (tid & 7) * 16,                             \
             &(Bptr)[(size_t)(n0 + r) * 256 + (koff) + (tid & 7) * 4]);           \
    }                                                                             \
    cp_commit();                                                                  \
} while (0)

#define COMPUTE_CHUNK(buf, DO_SPLIT)                                              \
do {                                                                              \
    const float*    As = (const float*)(smem + (buf) * STAGE_SZ);                 \
    const uint32_t* Au = (const uint32_t*)As;                                     \
    const uint32_t* Bs = (const uint32_t*)(smem + (buf) * STAGE_SZ + PLANE_A);    \
    _Pragma("unroll")                                                             \
    for (int ks = 0; ks < 4; ks++) {                                              \
        int c0 = ks * 8 + t;                                                      \
        uint32_t aHi[2][4], aLo[2][4];                                            \
        _Pragma("unroll")                                                         \
        for (int ma = 0; ma < 2; ma++) {                                          \
            int r0 = wm * 32 + ma * 16 + g;                                       \
            if (DO_SPLIT) {                                                       \
                float x0 = As[r0 * LDPA + c0];                                    \
                float x1 = As[(r0 + 8) * LDPA + c0];                              \
                float x2 = As[r0 * LDPA + c0 + 4];                                \
                float x3 = As[(r0 + 8) * LDPA + c0 + 4];                          \
                aHi[ma][0] = __float_as_uint(x0) & 0xFFFFE000u;                   \
                aHi[ma][1] = __float_as_uint(x1) & 0xFFFFE000u;                   \
                aHi[ma][2] = __float_as_uint(x2) & 0xFFFFE000u;                   \
                aHi[ma][3] = __float_as_uint(x3) & 0xFFFFE000u;                   \
                aLo[ma][0] = __float_as_uint(x0 - __uint_as_float(aHi[ma][0]));   \
                aLo[ma][1] = __float_as_uint(x1 - __uint_as_float(aHi[ma][1]));   \
                aLo[ma][2] = __float_as_uint(x2 - __uint_as_float(aHi[ma][2]));   \
                aLo[ma][3] = __float_as_uint(x3 - __uint_as_float(aHi[ma][3]));   \
            } else {                                                              \
                aHi[ma][0] = Au[r0 * LDPA + c0];                                  \
                aHi[ma][1] = Au[(r0 + 8) * LDPA + c0];                            \
                aHi[ma][2] = Au[r0 * LDPA + c0 + 4];                              \
                aHi[ma][3] = Au[(r0 + 8) * LDPA + c0 + 4];                        \
            }                                                                     \
        }                                                                         \
        _Pragma("unroll")                                                         \
        for (int na = 0; na < 8; na++) {                                          \
            int br = wn * 64 + na * 8 + g;                                        \
            uint2 bb2 = *(const uint2*)&Bs[br * LDPB + ks * 8 + 2 * t];           \
            _Pragma("unroll")                                                     \
            for (int ma = 0; ma < 2; ma++) {                                      \
                mma_tf32(acc[ma][na], aHi[ma], &bb2.x);                           \
                if (DO_SPLIT) mma_tf32(acc[ma][na], aLo[ma], &bb2.x);             \
            }                                                                     \
        }                                                                         \
    }                                                                             \
} while (0)

#define ACC_INIT()                                                                \
    float acc[2][8][4];                                                           \
    _Pragma("unroll")                                                             \
    for (int ma = 0; ma < 2; ma++)                                                \
        _Pragma("unroll")                                                         \
        for (int na = 0; na < 8; na++)                                            \
            _Pragma("unroll")                                                     \
            for (int q = 0; q < 4; q++) acc[ma][na][q] = 0.f

// ---------------- feature GEMM: branch 0 = Wh (split), 1 = Whp (plain) --------
__global__ void __launch_bounds__(256, 2)
gemm_feat(const float* __restrict__ h_t, const float* __restrict__ h_prev,
          const float* __restrict__ pki, const float* __restrict__ pkc,
          const float* __restrict__ b_intra,
          const float* __restrict__ a_intra, const float* __restrict__ a_cross,
          float* __restrict__ Wh, float* __restrict__ Whp,
          float* __restrict__ es, float* __restrict__ ed, float* __restrict__ esP,
          int M, int branch) {
    extern __shared__ char smem[];
    uint32_t sb = smem_u32(smem);
    const int tid = threadIdx.x;
    const int wid = tid >> 5, lane = tid & 31;
    const int wm = wid & 3, wn = wid >> 2;
    const int g = lane >> 2, t = lane & 3;
    const int m0 = blockIdx.x * BMM;
    const int n0 = blockIdx.y * 128;

    const float* A = branch ? h_prev : h_t;
    const float* B = branch ? pkc : pki;
    const float* avec = branch ? a_cross : a_intra;
    float* C = branch ? Whp : Wh;
    float* esT = branch ? esP : es;

    ACC_INIT();

    STAGE_CHUNK(A, B, 0, 0);
    for (int cc = 0; cc < 8; cc++) {
        int buf = cc & 1;
        if (cc < 7) { STAGE_CHUNK(A, B, (cc + 1) * 32, buf ^ 1); cp_wait<1>(); }
        else        cp_wait<0>();
        __syncthreads();
        if (branch == 0) COMPUTE_CHUNK(buf, 1);
        else             COMPUTE_CHUNK(buf, 0);
        __syncthreads();
    }

    if (branch == 0) {
        #pragma unroll
        for (int na = 0; na < 8; na++)
            #pragma unroll
            for (int j = 0; j < 2; j++) {
                float bv = __ldg(&b_intra[n0 + wn * 64 + na * 8 + 2 * t + j]);
                acc[0][na][j]     += bv;
                acc[0][na][2 + j] += bv;
                acc[1][na][j]     += bv;
                acc[1][na][2 + j] += bv;
            }
    }

    int rbase = m0 + wm * 32;
    {
        int h = blockIdx.y * 2 + wn;
        float e1[4] = {0.f, 0.f, 0.f, 0.f};
        float e2[4] = {0.f, 0.f, 0.f, 0.f};
        #pragma unroll
        for (int na = 0; na < 8; na++)
            #pragma unroll
            for (int j = 0; j < 2; j++) {
                int cw = na * 8 + 2 * t + j;
                float a1 = __ldg(&avec[h * 128 + cw]);
                float a2 = __ldg(&avec[h * 128 + 64 + cw]);
                e1[0] = fmaf(acc[0][na][j], a1, e1[0]);
                e1[1] = fmaf(acc[0][na][2 + j], a1, e1[1]);
                e1[2] = fmaf(acc[1][na][j], a1, e1[2]);
                e1[3] = fmaf(acc[1][na][2 + j], a1, e1[3]);
                e2[0] = fmaf(acc[0][na][j], a2, e2[0]);
                e2[1] = fmaf(acc[0][na][2 + j], a2, e2[1]);
                e2[2] = fmaf(acc[1][na][j], a2, e2[2]);
                e2[3] = fmaf(acc[1][na][2 + j], a2, e2[3]);
            }
        #pragma unroll
        for (int s = 0; s < 4; s++) {
            e1[s] += __shfl_xor_sync(0xffffffffu, e1[s], 1);
            e1[s] += __shfl_xor_sync(0xffffffffu, e1[s], 2);
            e2[s] += __shfl_xor_sync(0xffffffffu, e2[s], 1);
            e2[s] += __shfl_xor_sync(0xffffffffu, e2[s], 2);
        }
        if (t == 0) {
            int rows[4] = {rbase + g, rbase + 8 + g, rbase + 16 + g, rbase + 24 + g};
            #pragma unroll
            for (int s = 0; s < 4; s++) {
                if (rows[s] < M) {
                    esT[rows[s] * 4 + h] = e1[s];
                    if (branch == 0) ed[rows[s] * 4 + h] = e2[s];
                }
            }
        }
    }

    #pragma unroll
    for (int ma = 0; ma < 2; ma++) {
        int r0 = rbase + ma * 16 + g;
        #pragma unroll
        for (int na = 0; na < 8; na++) {
            int col = n0 + wn * 64 + na * 8 + 2 * t;
            if (r0 < M) {
                float2 v; v.x = acc[ma][na][0]; v.y = acc[ma][na][1];
                *(float2*)&C[(size_t)r0 * 256 + col] = v;
            }
            if (r0 + 8 < M) {
                float2 v; v.x = acc[ma][na][2]; v.y = acc[ma][na][3];
                *(float2*)&C[(size_t)(r0 + 8) * 256 + col] = v;
            }
        }
    }
}

// ---------------- gate GEMM ----------------
// which=1: gin (grid y=2).  which=2: grz_x = x@Wih_rz + bih+bhh (y=4).
// which=3: grz_h accumulate (y<4) + ghn (y 4,5), grid y=6.
__global__ void __launch_bounds__(256, 2)
gemm_gates(const float* __restrict__ X, const float* __restrict__ Hr,
           const float* __restrict__ pih, const float* __restrict__ phh,
           const float* __restrict__ bih, const float* __restrict__ bhh,
           float* __restrict__ grz, float* __restrict__ gin, float* __restrict__ ghn,
           int M, int which) {
    extern __shared__ char smem[];
    uint32_t sb = smem_u32(smem);
    const int tid = threadIdx.x;
    const int wid = tid >> 5, lane = tid & 31;
    const int wm = wid & 3, wn = wid >> 2;
    const int g = lane >> 2, t = lane & 3;
    const int m0 = blockIdx.x * BMM;
    const int by = blockIdx.y;
    // mode: 0=grz_x, 1=gin, 2=ghn, 3=grz_h(accum)
    int mode, n0;
    if (which == 1)      { mode = 1; n0 = by * 128; }
    else if (which == 2) { mode = 0; n0 = by * 128; }
    else                 { mode = (by < 4) ? 3 : 2; n0 = (by < 4) ? by * 128 : (by - 4) * 128; }

    const float* A1 = (mode == 2 || mode == 3) ? Hr : X;
    const float* B1 = (mode == 0) ? pih
                    : (mode == 1) ? pih + 512 * 256
                    : (mode == 3) ? phh
                    : phh + 512 * 256;

    ACC_INIT();

    STAGE_CHUNK(A1, B1, 0, 0);
    for (int cc = 0; cc < 8; cc++) {
        int buf = cc & 1;
        if (cc < 7) { STAGE_CHUNK(A1, B1, (cc + 1) * 32, buf ^ 1); cp_wait<1>(); }
        else        cp_wait<0>();
        __syncthreads();
        COMPUTE_CHUNK(buf, 0);
        __syncthreads();
    }

    int rbase = m0 + wm * 32;
    #pragma unroll
    for (int ma = 0; ma < 2; ma++) {
        int r0 = rbase + ma * 16 + g;
        #pragma unroll
        for (int na = 0; na < 8; na++) {
            int col = n0 + wn * 64 + na * 8 + 2 * t;
            float b0 = 0.f, b1 = 0.f;
            float* C; int ld;
            if (mode == 0) {
                b0 = __ldg(&bih[col]) + __ldg(&bhh[col]);
                b1 = __ldg(&bih[col + 1]) + __ldg(&bhh[col + 1]);
                C = grz; ld = 512;
            } else if (mode == 1) {
                b0 = __ldg(&bih[512 + col]); b1 = __ldg(&bih[512 + col + 1]);
                C = gin; ld = 256;
            } else if (mode == 2) {
                b0 = __ldg(&bhh[512 + col]); b1 = __ldg(&bhh[512 + col + 1]);
                C = ghn; ld = 256;
            } else {
                C = grz; ld = 512;   // accumulate into existing grz
            }
            if (r0 < M) {
                float2 v; v.x = acc[ma][na][0] + b0; v.y = acc[ma][na][1] + b1;
                if (mode == 3) {
                    float2 old = *(float2*)&C[(size_t)r0 * ld + col];
                    v.x += old.x; v.y += old.y;
                }
                *(float2*)&C[(size_t)r0 * ld + col] = v;
            }
            if (r0 + 8 < M) {
                float2 v; v.x = acc[ma][na][2] + b0; v.y = acc[ma][na][3] + b1;
                if (mode == 3) {
                    float2 old = *(float2*)&C[(size_t)(r0 + 8) * ld + col];
                    v.x += old.x; v.y += old.y;
                }
                *(float2*)&C[(size_t)(r0 + 8) * ld + col] = v;
            }
        }
    }
}

// ---------------- merged packs (tf32-round + K pair-interleave) ----------------
__global__ void pack_all(const float* __restrict__ Wi, const float* __restrict__ Wc,
                         const float* __restrict__ Wih, const float* __restrict__ Whh,
                         const float* __restrict__ ac,
                         float* __restrict__ pki, float* __restrict__ pkc,
                         float* __restrict__ pih, float* __restrict__ phh,
                         float* __restrict__ vmat) {
    int b = blockIdx.x;
    int tid = threadIdx.x;
    if (b < 512) {
        int o = (b & 255) * 256 + tid;
        int n = o >> 8, kp = o & 255;
        int f = (kp & 0xF8) | ((kp >> 1) & 3) | ((kp & 1) << 2);
        int h = n >> 6, dd = n & 63;
        const float* W = (b < 256) ? Wi : Wc;
        float* out = (b < 256) ? pki : pkc;
        out[o] = __uint_as_float(f2tf32(W[(h * 256 + f) * 64 + dd]));
    } else if (b < 2048) {
        int blk = (b < 1280) ? (b - 512) : (b - 1280);
        int o = blk * 256 + tid;
        int n = o >> 8, kp = o & 255;
        int k = (kp & 0xF8) | ((kp >> 1) & 3) | ((kp & 1) << 2);
        const float* W = (b < 1280) ? Wih : Whh;
        float* out = (b < 1280) ? pih : phh;
        out[o] = __uint_as_float(f2tf32(W[n * 256 + k]));
    } else {
        int o = (b - 2048) * 256 + tid;
        int f = o >> 2, h = o & 3;
        float s = 0.f;
        #pragma unroll 8
        for (int dd = 0; dd < 64; dd++)
            s = fmaf(Wc[(h * 256 + f) * 64 + dd], ac[h * 128 + 64 + dd], s);
        vmat[f * 4 + h] = s;
    }
}

// ---------------- intra-turn GAT: 4 nodes/block, float4, rounded-x store ------
__global__ __launch_bounds__(256)
void intra_agg(const float* __restrict__ Wh, const float* __restrict__ es,
               const float* __restrict__ ed, const float* __restrict__ ab,
               const int* __restrict__ src, const float* __restrict__ vmat,
               float* __restrict__ x, float* __restrict__ edX) {
    const int tid = threadIdx.x;
    const int d0 = blockIdx.x * 4;
    const int sub = tid >> 6;
    const int c4 = tid & 63;
    __shared__ int   ssrc[4][DEG_IN];
    __shared__ float se[4][NHEADS * DEG_IN];
    __shared__ float sred[4][2][NHEADS];

    if (tid < 64)
        ssrc[tid >> 4][tid & 15] = src[(d0 + (tid >> 4)) * DEG_IN + (tid & 15)];
    __syncthreads();

    {
        int s2 = tid >> 6;
        int r = tid & 63;
        int h = r >> 4, i = r & 15;
        float e = es[ssrc[s2][i] * 4 + h] + ed[(d0 + s2) * 4 + h] + ab[h];
        se[s2][r] = (e >= 0.f) ? e : ALPHA * e;
    }
    __syncthreads();

    if (tid < 16) {
        int s2 = tid >> 2, h = tid & 3;
        float* ep = &se[s2][h * 16];
        float m = -1e30f;
        #pragma unroll
        for (int i = 0; i < DEG_IN; i++) m = fmaxf(m, ep[i]);
        float s = 0.f;
        #pragma unroll
        for (int i = 0; i < DEG_IN; i++) { float ex = __expf(ep[i] - m); ep[i] = ex; s += ex; }
        float inv = 1.f / fmaxf(s, 1e-9f);
        #pragma unroll
        for (int i = 0; i < DEG_IN; i++) ep[i] *= inv;
    }
    __syncthreads();

    const int dd = d0 + sub;
    const int h = c4 >> 4;
    float4 acc = make_float4(0.f, 0.f, 0.f, 0.f);
    #pragma unroll
    for (int i = 0; i < DEG_IN; i++) {
        float w = se[sub][h * 16 + i];
        float4 v = *(const float4*)&Wh[(size_t)ssrc[sub][i] * 256 + c4 * 4];
        acc.x = fmaf(w, v.x, acc.x);
        acc.y = fmaf(w, v.y, acc.y);
        acc.z = fmaf(w, v.z, acc.z);
        acc.w = fmaf(w, v.w, acc.w);
    }
    float4 xr;
    xr.x = __uint_as_float(f2tf32(acc.x));
    xr.y = __uint_as_float(f2tf32(acc.y));
    xr.z = __uint_as_float(f2tf32(acc.z));
    xr.w = __uint_as_float(f2tf32(acc.w));
    *(float4*)&x[(size_t)dd * 256 + c4 * 4] = xr;

    float4 vm0 = *(const float4*)&vmat[(c4 * 4 + 0) * 4];
    float4 vm1 = *(const float4*)&vmat[(c4 * 4 + 1) * 4];
    float4 vm2 = *(const float4*)&vmat[(c4 * 4 + 2) * 4];
    float4 vm3 = *(const float4*)&vmat[(c4 * 4 + 3) * 4];
    float p[4];
    p[0] = acc.x * vm0.x + acc.y * vm1.x + acc.z * vm2.x + acc.w * vm3.x;
    p[1] = acc.x * vm0.y + acc.y * vm1.y + acc.z * vm2.y + acc.w * vm3.y;
    p[2] = acc.x * vm0.z + acc.y * vm1.z + acc.z * vm2.z + acc.w * vm3.z;
    p[3] = acc.x * vm0.w + acc.y * vm1.w + acc.z * vm2.w + acc.w * vm3.w;
    #pragma unroll
    for (int off = 16; off > 0; off >>= 1) {
        p[0] += __shfl_xor_sync(0xffffffffu, p[0], off);
        p[1] += __shfl_xor_sync(0xffffffffu, p[1], off);
        p[2] += __shfl_xor_sync(0xffffffffu, p[2], off);
        p[3] += __shfl_xor_sync(0xffffffffu, p[3], off);
    }
    if ((tid & 31) == 0) {
        int wp = (c4 >> 5);
        sred[sub][wp][0] = p[0];
        sred[sub][wp][1] = p[1];
        sred[sub][wp][2] = p[2];
        sred[sub][wp][3] = p[3];
    }
    __syncthreads();
    if (tid < 16) {
        int s2 = tid >> 2, hh = tid & 3;
        edX[(d0 + s2) * 4 + hh] = sred[s2][0][hh] + sred[s2][1][hh];
    }
}

// ---------------- cross-turn GAT: 4 nodes/block, dual h store ----------------
__global__ __launch_bounds__(256)
void cross_agg(const float* __restrict__ Whp, const float* __restrict__ esP,
               const float* __restrict__ edX, const int* __restrict__ src_c,
               const int* __restrict__ src_s, float* __restrict__ hout,
               float* __restrict__ hr) {
    const int tid = threadIdx.x;
    const int d0 = blockIdx.x * 4;
    const int sub = tid >> 6;
    const int c4 = tid & 63;
    __shared__ int   ssrc[4][16];
    __shared__ float se[4][64];

    if (tid < 64) {
        int s2 = tid >> 4, i = tid & 15;
        int dd = d0 + s2;
        ssrc[s2][i] = (i < 8) ? src_c[dd * 8 + i] : src_s[dd * 8 + (i - 8)];
    }
    __syncthreads();

    {
        int s2 = tid >> 6;
        int r = tid & 63;
        int which = r >> 5;
        int h = (r >> 3) & 3;
        int i = r & 7;
        int s = ssrc[s2][which * 8 + i];
        float e = esP[s * 4 + h] + edX[(d0 + s2) * 4 + h];
        se[s2][r] = (e >= 0.f) ? e : ALPHA * e;
    }
    __syncthreads();

    if (tid < 32) {
        int s2 = tid >> 3, grp = tid & 7;
        float* ep = &se[s2][(grp >> 2) * 32 + (grp & 3) * 8];
        float m = -1e30f;
        #pragma unroll
        for (int i = 0; i < DEG_C; i++) m = fmaxf(m, ep[i]);
        float s = 0.f;
        #pragma unroll
        for (int i = 0; i < DEG_C; i++) { float ex = __expf(ep[i] - m); ep[i] = ex; s += ex; }
        float inv = 1.f / fmaxf(s, 1e-9f);
        #pragma unroll
        for (int i = 0; i < DEG_C; i++) ep[i] *= inv;
    }
    __syncthreads();

    const int dd = d0 + sub;
    const int h = c4 >> 4;
    float4 acc = make_float4(0.f, 0.f, 0.f, 0.f);
    #pragma unroll
    for (int i = 0; i < DEG_C; i++) {
        float w = se[sub][h * 8 + i];
        float4 v = *(const float4*)&Whp[(size_t)ssrc[sub][i] * 256 + c4 * 4];
        acc.x = fmaf(w, v.x, acc.x);
        acc.y = fmaf(w, v.y, acc.y);
        acc.z = fmaf(w, v.z, acc.z);
        acc.w = fmaf(w, v.w, acc.w);
    }
    #pragma unroll
    for (int i = 0; i < DEG_C; i++) {
        float w = se[sub][32 + h * 8 + i];
        float4 v = *(const float4*)&Whp[(size_t)ssrc[sub][8 + i] * 256 + c4 * 4];
        acc.x = fmaf(w, v.x, acc.x);
        acc.y = fmaf(w, v.y, acc.y);
        acc.z = fmaf(w, v.z, acc.z);
        acc.w = fmaf(w, v.w, acc.w);
    }
    float4 o;
    o.x = 0.5f * acc.x; o.y = 0.5f * acc.y; o.z = 0.5f * acc.z; o.w = 0.5f * acc.w;
    *(float4*)&hout[(size_t)dd * 256 + c4 * 4] = o;
    float4 orr;
    orr.x = __uint_as_float(f2tf32(o.x));
    orr.y = __uint_as_float(f2tf32(o.y));
    orr.z = __uint_as_float(f2tf32(o.z));
    orr.w = __uint_as_float(f2tf32(o.w));
    *(float4*)&hr[(size_t)dd * 256 + c4 * 4] = orr;
}

// ---------------- GRU elementwise (float4, MUFU transcendentals) -------------
__global__ void gru_kernel(const float* __restrict__ grz, const float* __restrict__ gin,
                           const float* __restrict__ ghn, const float* __restrict__ h,
                           float* __restrict__ out) {
    int idx = blockIdx.x * 256 + threadIdx.x;
    int node = idx >> 6, c = idx & 63;
    float4 rr = *(const float4*)&grz[(size_t)node * 512 + c * 4];
    float4 zz = *(const float4*)&grz[(size_t)node * 512 + 256 + c * 4];
    float4 gn = *(const float4*)&gin[(size_t)idx * 4];
    float4 hn = *(const float4*)&ghn[(size_t)idx * 4];
    float4 hh = *(const float4*)&h[(size_t)idx * 4];
    float4 o;
    { float r = fsig(rr.x), z = fsig(zz.x);
      o.x = (1.f - z) * ftanh(gn.x + r * hn.x) + z * hh.x; }
    { float r = fsig(rr.y), z = fsig(zz.y);
      o.y = (1.f - z) * ftanh(gn.y + r * hn.y) + z * hh.y; }
    { float r = fsig(rr.z), z = fsig(zz.z);
      o.z = (1.f - z) * ftanh(gn.z + r * hn.z) + z * hh.z; }
    { float r = fsig(rr.w), z = fsig(zz.w);
      o.w = (1.f - z) * ftanh(gn.w + r * hn.w) + z * hh.w; }
    *(float4*)&out[(size_t)idx * 4] = o;
}

// ---------------- host launcher (fork-join over two streams) ----------------
extern "C" void kernel_launch(void* const* d_in, const int* in_sizes, int n_in,
                              void* d_out, int out_size) {
    const float* h_t      = (const float*)d_in[0];
    const float* h_prev   = (const float*)d_in[1];
    const float* W_intra  = (const float*)d_in[2];
    const float* b_intra  = (const float*)d_in[3];
    const float* a_intra  = (const float*)d_in[4];
    const float* ab_intra = (const float*)d_in[5];
    const float* W_cross  = (const float*)d_in[6];
    const float* a_cross  = (const float*)d_in[7];
    const float* W_ih     = (const float*)d_in[8];
    const float* W_hh     = (const float*)d_in[9];
    const float* b_ih     = (const float*)d_in[10];
    const float* b_hh     = (const float*)d_in[11];
    const int*   src_in   = (const int*)d_in[12];
    const int*   src_c    = (const int*)d_in[14];
    const int*   src_s    = (const int*)d_in[16];
    float* out = (float*)d_out;

    float *p_Wh, *p_x, *p_Whp, *p_h, *p_hr, *p_grz, *p_gin, *p_ghn;
    float *p_pki, *p_pkc, *p_pih, *p_phh, *p_vm, *p_es, *p_ed, *p_esP, *p_edX;
    cudaGetSymbolAddress((void**)&p_Wh,  d_Wh);
    cudaGetSymbolAddress((void**)&p_x,   d_x);
    cudaGetSymbolAddress((void**)&p_Whp, d_Whp);
    cudaGetSymbolAddress((void**)&p_h,   d_h);
    cudaGetSymbolAddress((void**)&p_hr,  d_hr);
    cudaGetSymbolAddress((void**)&p_grz, d_grz);
    cudaGetSymbolAddress((void**)&p_gin, d_gin);
    cudaGetSymbolAddress((void**)&p_ghn, d_ghn);
    cudaGetSymbolAddress((void**)&p_pki, d_pk_intra);
    cudaGetSymbolAddress((void**)&p_pkc, d_pk_cross);
    cudaGetSymbolAddress((void**)&p_pih, d_pih);
    cudaGetSymbolAddress((void**)&p_phh, d_phh);
    cudaGetSymbolAddress((void**)&p_vm,  d_vmat);
    cudaGetSymbolAddress((void**)&p_es,  d_es);
    cudaGetSymbolAddress((void**)&p_ed,  d_ed);
    cudaGetSymbolAddress((void**)&p_esP, d_esP);
    cudaGetSymbolAddress((void**)&p_edX, d_edX);

    cudaFuncSetAttribute(gemm_feat,  cudaFuncAttributeMaxDynamicSharedMemorySize, SMEMSZ);
    cudaFuncSetAttribute(gemm_gates, cudaFuncAttributeMaxDynamicSharedMemorySize, SMEMSZ);

    cudaStream_t s1;
    cudaStreamCreateWithFlags(&s1, cudaStreamNonBlocking);
    cudaEvent_t e0, e1, e2;
    cudaEventCreateWithFlags(&e0, cudaEventDisableTiming);
    cudaEventCreateWithFlags(&e1, cudaEventDisableTiming);
    cudaEventCreateWithFlags(&e2, cudaEventDisableTiming);

    dim3 gF((NN + BMM - 1) / BMM, 2);
    dim3 gGin((NN + BMM - 1) / BMM, 2);
    dim3 gGrzX((NN + BMM - 1) / BMM, 4);
    dim3 gGpost((NN + BMM - 1) / BMM, 6);

    // s0: packs
    pack_all<<<2052, 256>>>(W_intra, W_cross, W_ih, W_hh, a_cross,
                            p_pki, p_pkc, p_pih, p_phh, p_vm);
    // fork s1 after packs
    cudaEventRecord(e0, 0);
    cudaStreamWaitEvent(s1, e0, 0);

    // s0: Wh branch (split) -> intra_agg ; s1: Whp branch (plain)
    gemm_feat<<<gF, 256, SMEMSZ>>>(h_t, h_prev, p_pki, p_pkc, b_intra,
                                   a_intra, a_cross, p_Wh, p_Whp,
                                   p_es, p_ed, p_esP, NN, 0);
    gemm_feat<<<gF, 256, SMEMSZ, s1>>>(h_t, h_prev, p_pki, p_pkc, b_intra,
                                       a_intra, a_cross, p_Wh, p_Whp,
                                       p_es, p_ed, p_esP, NN, 1);
    intra_agg<<<NN / 4, 256>>>(p_Wh, p_es, p_ed, ab_intra, src_in, p_vm, p_x, p_edX);

    // s1: cross_agg (needs edX from s0 + Whp/esP from s1)
    cudaEventRecord(e1, 0);
    cudaStreamWaitEvent(s1, e1, 0);
    cross_agg<<<NN / 4, 256, 0, s1>>>(p_Whp, p_esP, p_edX, src_c, src_s, p_h, p_hr);

    // s0 concurrently: gin + grz_x (need only x)
    gemm_gates<<<gGin, 256, SMEMSZ>>>(p_x, p_hr, p_pih, p_phh, b_ih, b_hh,
                                      p_grz, p_gin, p_ghn, NN, 1);
    gemm_gates<<<gGrzX, 256, SMEMSZ>>>(p_x, p_hr, p_pih, p_phh, b_ih, b_hh,
                                       p_grz, p_gin, p_ghn, NN, 2);

    // join s1 -> s0, then grz_h accumulate + ghn, gru
    cudaEventRecord(e2, s1);
    cudaStreamWaitEvent(0, e2, 0);
    gemm_gates<<<gGpost, 256, SMEMSZ>>>(p_x, p_hr, p_pih, p_phh, b_ih, b_hh,
                                        p_grz, p_gin, p_ghn, NN, 3);
    gru_kernel<<<NN / 4, 256>>>(p_grz, p_gin, p_ghn, p_h, out);

    cudaEventDestroy(e0);
    cudaEventDestroy(e1);
    cudaEventDestroy(e2);
    cudaStreamDestroy(s1);
}

// round 17
// speedup vs baseline: 1.1312x; 1.1312x over previous
#include <cuda_runtime.h>
#include <cuda_bf16.h>
#include <math.h>
#include <stdint.h>

// ---------------- problem constants ----------------
#define NN      50000
#define NPREV   50000
#define NFEATS  256
#define NHID    256
#define NHEADS  4
#define HD      64
#define DEG_IN  16
#define DEG_C   8
#define ALPHA   0.2f

// ---------------- device scratch ----------------
__device__ float d_Wh  [NN * NHID];
__device__ float d_x   [NN * NHID];
__device__ float d_Whp [NPREV * NHID];
__device__ float d_h   [NN * NHID];
__device__ float d_hr  [NN * NHID];
__device__ float d_grz [NN * 512];
__device__ float d_gin [NN * NHID];
__device__ float d_ghn [NN * NHID];
__device__ float d_pk_intra[NHID * NFEATS];
__device__ float d_pk_cross[NHID * NHID];
__device__ float d_pih[768 * 256];
__device__ float d_phh[768 * 256];
__device__ float d_vmat[NFEATS * NHEADS];
__device__ float d_es [NN * NHEADS];
__device__ float d_ed [NN * NHEADS];
__device__ float d_esP[NPREV * NHEADS];
__device__ float d_edX[NN * NHEADS];

// ---------------- helpers ----------------
__device__ __forceinline__ uint32_t smem_u32(const void* p) {
    uint32_t a;
    asm("{ .reg .u64 t; cvta.to.shared.u64 t, %1; cvt.u32.u64 %0, t; }" : "=r"(a) : "l"(p));
    return a;
}
__device__ __forceinline__ uint32_t f2tf32(float x) {
    uint32_t r;
    asm("cvt.rna.tf32.f32 %0, %1;" : "=r"(r) : "f"(x));
    return r;
}
__device__ __forceinline__ void cp16(uint32_t dst, const void* src) {
    asm volatile("cp.async.cg.shared.global [%0], [%1], 16;" :: "r"(dst), "l"(src));
}
__device__ __forceinline__ void cp_commit() {
    asm volatile("cp.async.commit_group;" ::: "memory");
}
template<int N>
__device__ __forceinline__ void cp_wait() {
    asm volatile("cp.async.wait_group %0;" :: "n"(N) : "memory");
}
__device__ __forceinline__ void mma_tf32(float* d, const uint32_t* a, const uint32_t* b) {
    asm volatile(
        "mma.sync.aligned.m16n8k8.row.col.f32.tf32.tf32.f32 "
        "{%0,%1,%2,%3},{%4,%5,%6,%7},{%8,%9},{%0,%1,%2,%3};"
        : "+f"(d[0]), "+f"(d[1]), "+f"(d[2]), "+f"(d[3])
        : "r"(a[0]), "r"(a[1]), "r"(a[2]), "r"(a[3]), "r"(b[0]), "r"(b[1]));
}
__device__ __forceinline__ float fsig(float x) {
    return 1.f / (1.f + __expf(-x));
}
__device__ __forceinline__ float ftanh(float x) {
    float e = __expf(2.f * x);
    return 1.f - 2.f / (e + 1.f);
}
// L2-cached gather (bypass L1)
__device__ __forceinline__ float4 ldcg4(const float* p) {
    float4 v;
    asm volatile("ld.global.cg.v4.f32 {%0,%1,%2,%3}, [%4];"
        : "=f"(v.x), "=f"(v.y), "=f"(v.z), "=f"(v.w) : "l"(p));
    return v;
}

#define BMM 128
#define LDPA 36
#define LDPB 40
#define PLANE_A  (128 * LDPA * 4)
#define PLANE_BB (128 * LDPB * 4)
#define STAGE_SZ (PLANE_A + PLANE_BB)
#define SMEMSZ   (2 * STAGE_SZ)

#define STAGE_CHUNK(Aptr, Bptr, koff, buf)                                        \
do {                                                                              \
    uint32_t abase = sb + (buf) * STAGE_SZ;                                       \
    uint32_t bbase = abase + PLANE_A;                                             \
    _Pragma("unroll")                                                             \
    for (int j = 0; j < 4; j++) {                                                 \
        int r = (tid >> 3) + j * 32;                                              \
        int row = m0 + r; if (row >= M) row = M - 1;                              \
        cp16(abase + r * (LDPA * 4) + (tid & 7) * 16,                             \
             &(Aptr)[(size_t)row * 256 + (koff) + (tid & 7) * 4]);                \
    }                                                                             \
    _Pragma("unroll")                                                             \
    for (int j = 0; j < 4; j++) {                                                 \
        int r = (tid >> 3) + j * 32;                                              \
        cp16(bbase + r * (LDPB * 4) + (tid & 7) * 16,                             \
             &(Bptr)[(size_t)(n0 + r) * 256 + (koff) + (tid & 7) * 4]);           \
    }                                                                             \
    cp_commit();                                                                  \
} while (0)

#define COMPUTE_CHUNK(buf, DO_SPLIT)                                              \
do {                                                                              \
    const float*    As = (const float*)(smem + (buf) * STAGE_SZ);                 \
    const uint32_t* Au = (const uint32_t*)As;                                     \
    const uint32_t* Bs = (const uint32_t*)(smem + (buf) * STAGE_SZ + PLANE_A);    \
    _Pragma("unroll")                                                             \
    for (int ks = 0; ks < 4; ks++) {                                              \
        int c0 = ks * 8 + t;                                                      \
        uint32_t aHi[2][4], aLo[2][4];                                            \
        _Pragma("unroll")                                                         \
        for (int ma = 0; ma < 2; ma++) {                                          \
            int r0 = wm * 32 + ma * 16 + g;                                       \
            if (DO_SPLIT) {                                                       \
                float x0 = As[r0 * LDPA + c0];                                    \
                float x1 = As[(r0 + 8) * LDPA + c0];                              \
                float x2 = As[r0 * LDPA + c0 + 4];                                \
                float x3 = As[(r0 + 8) * LDPA + c0 + 4];                          \
                aHi[ma][0] = __float_as_uint(x0) & 0xFFFFE000u;                   \
                aHi[ma][1] = __float_as_uint(x1) & 0xFFFFE000u;                   \
                aHi[ma][2] = __float_as_uint(x2) & 0xFFFFE000u;                   \
                aHi[ma][3] = __float_as_uint(x3) & 0xFFFFE000u;                   \
                aLo[ma][0] = __float_as_uint(x0 - __uint_as_float(aHi[ma][0]));   \
                aLo[ma][1] = __float_as_uint(x1 - __uint_as_float(aHi[ma][1]));   \
                aLo[ma][2] = __float_as_uint(x2 - __uint_as_float(aHi[ma][2]));   \
                aLo[ma][3] = __float_as_uint(x3 - __uint_as_float(aHi[ma][3]));   \
            } else {                                                              \
                aHi[ma][0] = Au[r0 * LDPA + c0];                                  \
                aHi[ma][1] = Au[(r0 + 8) * LDPA + c0];                            \
                aHi[ma][2] = Au[r0 * LDPA + c0 + 4];                              \
                aHi[ma][3] = Au[(r0 + 8) * LDPA + c0 + 4];                        \
            }                                                                     \
        }                                                                         \
        _Pragma("unroll")                                                         \
        for (int na = 0; na < 8; na++) {                                          \
            int br = wn * 64 + na * 8 + g;                                        \
            uint2 bb2 = *(const uint2*)&Bs[br * LDPB + ks * 8 + 2 * t];           \
            _Pragma("unroll")                                                     \
            for (int ma = 0; ma < 2; ma++) {                                      \
                mma_tf32(acc[ma][na], aHi[ma], &bb2.x);                           \
                if (DO_SPLIT) mma_tf32(acc[ma][na], aLo[ma], &bb2.x);             \
            }                                                                     \
        }                                                                         \
    }                                                                             \
} while (0)

#define ACC_INIT()                                                                \
    float acc[2][8][4];                                                           \
    _Pragma("unroll")                                                             \
    for (int ma = 0; ma < 2; ma++)                                                \
        _Pragma("unroll")                                                         \
        for (int na = 0; na < 8; na++)                                            \
            _Pragma("unroll")                                                     \
            for (int q = 0; q < 4; q++) acc[ma][na][q] = 0.f

// ---------------- feature GEMM: branch 0 = Wh (split), 1 = Whp (plain) --------
__global__ void __launch_bounds__(256, 2)
gemm_feat(const float* __restrict__ h_t, const float* __restrict__ h_prev,
          const float* __restrict__ pki, const float* __restrict__ pkc,
          const float* __restrict__ b_intra,
          const float* __restrict__ a_intra, const float* __restrict__ a_cross,
          float* __restrict__ Wh, float* __restrict__ Whp,
          float* __restrict__ es, float* __restrict__ ed, float* __restrict__ esP,
          int M, int branch) {
    extern __shared__ char smem[];
    uint32_t sb = smem_u32(smem);
    const int tid = threadIdx.x;
    const int wid = tid >> 5, lane = tid & 31;
    const int wm = wid & 3, wn = wid >> 2;
    const int g = lane >> 2, t = lane & 3;
    const int m0 = blockIdx.x * BMM;
    const int n0 = blockIdx.y * 128;

    const float* A = branch ? h_prev : h_t;
    const float* B = branch ? pkc : pki;
    const float* avec = branch ? a_cross : a_intra;
    float* C = branch ? Whp : Wh;
    float* esT = branch ? esP : es;

    ACC_INIT();

    STAGE_CHUNK(A, B, 0, 0);
    for (int cc = 0; cc < 8; cc++) {
        int buf = cc & 1;
        if (cc < 7) { STAGE_CHUNK(A, B, (cc + 1) * 32, buf ^ 1); cp_wait<1>(); }
        else        cp_wait<0>();
        __syncthreads();
        if (branch == 0) COMPUTE_CHUNK(buf, 1);
        else             COMPUTE_CHUNK(buf, 0);
        __syncthreads();
    }

    if (branch == 0) {
        #pragma unroll
        for (int na = 0; na < 8; na++)
            #pragma unroll
            for (int j = 0; j < 2; j++) {
                float bv = __ldg(&b_intra[n0 + wn * 64 + na * 8 + 2 * t + j]);
                acc[0][na][j]     += bv;
                acc[0][na][2 + j] += bv;
                acc[1][na][j]     += bv;
                acc[1][na][2 + j] += bv;
            }
    }

    int rbase = m0 + wm * 32;
    {
        int h = blockIdx.y * 2 + wn;
        float e1[4] = {0.f, 0.f, 0.f, 0.f};
        float e2[4] = {0.f, 0.f, 0.f, 0.f};
        #pragma unroll
        for (int na = 0; na < 8; na++)
            #pragma unroll
            for (int j = 0; j < 2; j++) {
                int cw = na * 8 + 2 * t + j;
                float a1 = __ldg(&avec[h * 128 + cw]);
                float a2 = __ldg(&avec[h * 128 + 64 + cw]);
                e1[0] = fmaf(acc[0][na][j], a1, e1[0]);
                e1[1] = fmaf(acc[0][na][2 + j], a1, e1[1]);
                e1[2] = fmaf(acc[1][na][j], a1, e1[2]);
                e1[3] = fmaf(acc[1][na][2 + j], a1, e1[3]);
                e2[0] = fmaf(acc[0][na][j], a2, e2[0]);
                e2[1] = fmaf(acc[0][na][2 + j], a2, e2[1]);
                e2[2] = fmaf(acc[1][na][j], a2, e2[2]);
                e2[3] = fmaf(acc[1][na][2 + j], a2, e2[3]);
            }
        #pragma unroll
        for (int s = 0; s < 4; s++) {
            e1[s] += __shfl_xor_sync(0xffffffffu, e1[s], 1);
            e1[s] += __shfl_xor_sync(0xffffffffu, e1[s], 2);
            e2[s] += __shfl_xor_sync(0xffffffffu, e2[s], 1);
            e2[s] += __shfl_xor_sync(0xffffffffu, e2[s], 2);
        }
        if (t == 0) {
            int rows[4] = {rbase + g, rbase + 8 + g, rbase + 16 + g, rbase + 24 + g};
            #pragma unroll
            for (int s = 0; s < 4; s++) {
                if (rows[s] < M) {
                    esT[rows[s] * 4 + h] = e1[s];
                    if (branch == 0) ed[rows[s] * 4 + h] = e2[s];
                }
            }
        }
    }

    #pragma unroll
    for (int ma = 0; ma < 2; ma++) {
        int r0 = rbase + ma * 16 + g;
        #pragma unroll
        for (int na = 0; na < 8; na++) {
            int col = n0 + wn * 64 + na * 8 + 2 * t;
            if (r0 < M) {
                float2 v; v.x = acc[ma][na][0]; v.y = acc[ma][na][1];
                *(float2*)&C[(size_t)r0 * 256 + col] = v;
            }
            if (r0 + 8 < M) {
                float2 v; v.x = acc[ma][na][2]; v.y = acc[ma][na][3];
                *(float2*)&C[(size_t)(r0 + 8) * 256 + col] = v;
            }
        }
    }
}

// ---------------- gate GEMM ----------------
// which=1: gin only (grid y=2). which=0: grz (y<4, K=512) + ghn (y 4,5), grid y=6.
__global__ void __launch_bounds__(256, 2)
gemm_gates(const float* __restrict__ X, const float* __restrict__ Hr,
           const float* __restrict__ pih, const float* __restrict__ phh,
           const float* __restrict__ bih, const float* __restrict__ bhh,
           float* __restrict__ grz, float* __restrict__ gin, float* __restrict__ ghn,
           int M, int which) {
    extern __shared__ char smem[];
    uint32_t sb = smem_u32(smem);
    const int tid = threadIdx.x;
    const int wid = tid >> 5, lane = tid & 31;
    const int wm = wid & 3, wn = wid >> 2;
    const int g = lane >> 2, t = lane & 3;
    const int m0 = blockIdx.x * BMM;
    const int by = blockIdx.y;
    const int mode = (which == 1) ? 1 : ((by < 4) ? 0 : 2);
    const int n0 = (which == 1) ? by * 128 : ((by < 4) ? by * 128 : (by - 4) * 128);

    const float* A1 = (mode == 2) ? Hr : X;
    const float* B1 = (mode == 0) ? pih : ((mode == 1) ? pih + 512 * 256 : phh + 512 * 256);
    const int nch = (mode == 0) ? 16 : 8;

    ACC_INIT();

    STAGE_CHUNK(A1, B1, 0, 0);
    for (int cc = 0; cc < nch; cc++) {
        int buf = cc & 1;
        if (cc < nch - 1) {
            int nc = cc + 1;
            const float* Ap = (mode == 0 && nc >= 8) ? Hr : A1;
            const float* Bp = (mode == 0 && nc >= 8) ? phh : B1;
            int koff = (nc & 7) * 32;
            STAGE_CHUNK(Ap, Bp, koff, buf ^ 1);
            cp_wait<1>();
        } else {
            cp_wait<0>();
        }
        __syncthreads();
        COMPUTE_CHUNK(buf, 0);
        __syncthreads();
    }

    int rbase = m0 + wm * 32;
    #pragma unroll
    for (int ma = 0; ma < 2; ma++) {
        int r0 = rbase + ma * 16 + g;
        #pragma unroll
        for (int na = 0; na < 8; na++) {
            int col = n0 + wn * 64 + na * 8 + 2 * t;
            float b0, b1;
            float* C; int ld;
            if (mode == 0) {
                b0 = __ldg(&bih[col]) + __ldg(&bhh[col]);
                b1 = __ldg(&bih[col + 1]) + __ldg(&bhh[col + 1]);
                C = grz; ld = 512;
            } else if (mode == 1) {
                b0 = __ldg(&bih[512 + col]); b1 = __ldg(&bih[512 + col + 1]);
                C = gin; ld = 256;
            } else {
                b0 = __ldg(&bhh[512 + col]); b1 = __ldg(&bhh[512 + col + 1]);
                C = ghn; ld = 256;
            }
            if (r0 < M) {
                float2 v; v.x = acc[ma][na][0] + b0; v.y = acc[ma][na][1] + b1;
                *(float2*)&C[(size_t)r0 * ld + col] = v;
            }
            if (r0 + 8 < M) {
                float2 v; v.x = acc[ma][na][2] + b0; v.y = acc[ma][na][3] + b1;
                *(float2*)&C[(size_t)(r0 + 8) * ld + col] = v;
            }
        }
    }
}

// ---------------- merged packs (tf32-round + K pair-interleave) ----------------
__global__ void pack_all(const float* __restrict__ Wi, const float* __restrict__ Wc,
                         const float* __restrict__ Wih, const float* __restrict__ Whh,
                         const float* __restrict__ ac,
                         float* __restrict__ pki, float* __restrict__ pkc,
                         float* __restrict__ pih, float* __restrict__ phh,
                         float* __restrict__ vmat) {
    int b = blockIdx.x;
    int tid = threadIdx.x;
    if (b < 512) {
        int o = (b & 255) * 256 + tid;
        int n = o >> 8, kp = o & 255;
        int f = (kp & 0xF8) | ((kp >> 1) & 3) | ((kp & 1) << 2);
        int h = n >> 6, dd = n & 63;
        const float* W = (b < 256) ? Wi : Wc;
        float* out = (b < 256) ? pki : pkc;
        out[o] = __uint_as_float(f2tf32(W[(h * 256 + f) * 64 + dd]));
    } else if (b < 2048) {
        int blk = (b < 1280) ? (b - 512) : (b - 1280);
        int o = blk * 256 + tid;
        int n = o >> 8, kp = o & 255;
        int k = (kp & 0xF8) | ((kp >> 1) & 3) | ((kp & 1) << 2);
        const float* W = (b < 1280) ? Wih : Whh;
        float* out = (b < 1280) ? pih : phh;
        out[o] = __uint_as_float(f2tf32(W[n * 256 + k]));
    } else {
        int o = (b - 2048) * 256 + tid;
        int f = o >> 2, h = o & 3;
        float s = 0.f;
        #pragma unroll 8
        for (int dd = 0; dd < 64; dd++)
            s = fmaf(Wc[(h * 256 + f) * 64 + dd], ac[h * 128 + 64 + dd], s);
        vmat[f * 4 + h] = s;
    }
}

// ---------------- intra-turn GAT: 4 nodes/block, L2-path gathers --------------
__global__ __launch_bounds__(256)
void intra_agg(const float* __restrict__ Wh, const float* __restrict__ es,
               const float* __restrict__ ed, const float* __restrict__ ab,
               const int* __restrict__ src, const float* __restrict__ vmat,
               float* __restrict__ x, float* __restrict__ edX) {
    const int tid = threadIdx.x;
    const int d0 = blockIdx.x * 4;
    const int sub = tid >> 6;
    const int c4 = tid & 63;
    __shared__ int   ssrc[4][DEG_IN];
    __shared__ float se[4][NHEADS * DEG_IN];
    __shared__ float sred[4][2][NHEADS];

    if (tid < 64)
        ssrc[tid >> 4][tid & 15] = src[(d0 + (tid >> 4)) * DEG_IN + (tid & 15)];
    __syncthreads();

    {
        int s2 = tid >> 6;
        int r = tid & 63;
        int h = r >> 4, i = r & 15;
        float e = es[ssrc[s2][i] * 4 + h] + ed[(d0 + s2) * 4 + h] + ab[h];
        se[s2][r] = (e >= 0.f) ? e : ALPHA * e;
    }
    __syncthreads();

    if (tid < 16) {
        int s2 = tid >> 2, h = tid & 3;
        float* ep = &se[s2][h * 16];
        float m = -1e30f;
        #pragma unroll
        for (int i = 0; i < DEG_IN; i++) m = fmaxf(m, ep[i]);
        float s = 0.f;
        #pragma unroll
        for (int i = 0; i < DEG_IN; i++) { float ex = __expf(ep[i] - m); ep[i] = ex; s += ex; }
        float inv = 1.f / fmaxf(s, 1e-9f);
        #pragma unroll
        for (int i = 0; i < DEG_IN; i++) ep[i] *= inv;
    }
    __syncthreads();

    const int dd = d0 + sub;
    const int h = c4 >> 4;
    float4 acc = make_float4(0.f, 0.f, 0.f, 0.f);
    #pragma unroll
    for (int i = 0; i < DEG_IN; i++) {
        float w = se[sub][h * 16 + i];
        float4 v = ldcg4(&Wh[(size_t)ssrc[sub][i] * 256 + c4 * 4]);
        acc.x = fmaf(w, v.x, acc.x);
        acc.y = fmaf(w, v.y, acc.y);
        acc.z = fmaf(w, v.z, acc.z);
        acc.w = fmaf(w, v.w, acc.w);
    }
    float4 xr;
    xr.x = __uint_as_float(f2tf32(acc.x));
    xr.y = __uint_as_float(f2tf32(acc.y));
    xr.z = __uint_as_float(f2tf32(acc.z));
    xr.w = __uint_as_float(f2tf32(acc.w));
    *(float4*)&x[(size_t)dd * 256 + c4 * 4] = xr;

    float4 vm0 = *(const float4*)&vmat[(c4 * 4 + 0) * 4];
    float4 vm1 = *(const float4*)&vmat[(c4 * 4 + 1) * 4];
    float4 vm2 = *(const float4*)&vmat[(c4 * 4 + 2) * 4];
    float4 vm3 = *(const float4*)&vmat[(c4 * 4 + 3) * 4];
    float p[4];
    p[0] = acc.x * vm0.x + acc.y * vm1.x + acc.z * vm2.x + acc.w * vm3.x;
    p[1] = acc.x * vm0.y + acc.y * vm1.y + acc.z * vm2.y + acc.w * vm3.y;
    p[2] = acc.x * vm0.z + acc.y * vm1.z + acc.z * vm2.z + acc.w * vm3.z;
    p[3] = acc.x * vm0.w + acc.y * vm1.w + acc.z * vm2.w + acc.w * vm3.w;
    #pragma unroll
    for (int off = 16; off > 0; off >>= 1) {
        p[0] += __shfl_xor_sync(0xffffffffu, p[0], off);
        p[1] += __shfl_xor_sync(0xffffffffu, p[1], off);
        p[2] += __shfl_xor_sync(0xffffffffu, p[2], off);
        p[3] += __shfl_xor_sync(0xffffffffu, p[3], off);
    }
    if ((tid & 31) == 0) {
        int wp = (c4 >> 5);
        sred[sub][wp][0] = p[0];
        sred[sub][wp][1] = p[1];
        sred[sub][wp][2] = p[2];
        sred[sub][wp][3] = p[3];
    }
    __syncthreads();
    if (tid < 16) {
        int s2 = tid >> 2, hh = tid & 3;
        edX[(d0 + s2) * 4 + hh] = sred[s2][0][hh] + sred[s2][1][hh];
    }
}

// ---------------- cross-turn GAT: 4 nodes/block, L2-path gathers --------------
__global__ __launch_bounds__(256)
void cross_agg(const float* __restrict__ Whp, const float* __restrict__ esP,
               const float* __restrict__ edX, const int* __restrict__ src_c,
               const int* __restrict__ src_s, float* __restrict__ hout,
               float* __restrict__ hr) {
    const int tid = threadIdx.x;
    const int d0 = blockIdx.x * 4;
    const int sub = tid >> 6;
    const int c4 = tid & 63;
    __shared__ int   ssrc[4][16];
    __shared__ float se[4][64];

    if (tid < 64) {
        int s2 = tid >> 4, i = tid & 15;
        int dd = d0 + s2;
        ssrc[s2][i] = (i < 8) ? src_c[dd * 8 + i] : src_s[dd * 8 + (i - 8)];
    }
    __syncthreads();

    {
        int s2 = tid >> 6;
        int r = tid & 63;
        int which = r >> 5;
        int h = (r >> 3) & 3;
        int i = r & 7;
        int s = ssrc[s2][which * 8 + i];
        float e = esP[s * 4 + h] + edX[(d0 + s2) * 4 + h];
        se[s2][r] = (e >= 0.f) ? e : ALPHA * e;
    }
    __syncthreads();

    if (tid < 32) {
        int s2 = tid >> 3, grp = tid & 7;
        float* ep = &se[s2][(grp >> 2) * 32 + (grp & 3) * 8];
        float m = -1e30f;
        #pragma unroll
        for (int i = 0; i < DEG_C; i++) m = fmaxf(m, ep[i]);
        float s = 0.f;
        #pragma unroll
        for (int i = 0; i < DEG_C; i++) { float ex = __expf(ep[i] - m); ep[i] = ex; s += ex; }
        float inv = 1.f / fmaxf(s, 1e-9f);
        #pragma unroll
        for (int i = 0; i < DEG_C; i++) ep[i] *= inv;
    }
    __syncthreads();

    const int dd = d0 + sub;
    const int h = c4 >> 4;
    float4 acc = make_float4(0.f, 0.f, 0.f, 0.f);
    #pragma unroll
    for (int i = 0; i < DEG_C; i++) {
        float w = se[sub][h * 8 + i];
        float4 v = ldcg4(&Whp[(size_t)ssrc[sub][i] * 256 + c4 * 4]);
        acc.x = fmaf(w, v.x, acc.x);
        acc.y = fmaf(w, v.y, acc.y);
        acc.z = fmaf(w, v.z, acc.z);
        acc.w = fmaf(w, v.w, acc.w);
    }
    #pragma unroll
    for (int i = 0; i < DEG_C; i++) {
        float w = se[sub][32 + h * 8 + i];
        float4 v = ldcg4(&Whp[(size_t)ssrc[sub][8 + i] * 256 + c4 * 4]);
        acc.x = fmaf(w, v.x, acc.x);
        acc.y = fmaf(w, v.y, acc.y);
        acc.z = fmaf(w, v.z, acc.z);
        acc.w = fmaf(w, v.w, acc.w);
    }
    float4 o;
    o.x = 0.5f * acc.x; o.y = 0.5f * acc.y; o.z = 0.5f * acc.z; o.w = 0.5f * acc.w;
    *(float4*)&hout[(size_t)dd * 256 + c4 * 4] = o;
    float4 orr;
    orr.x = __uint_as_float(f2tf32(o.x));
    orr.y = __uint_as_float(f2tf32(o.y));
    orr.z = __uint_as_float(f2tf32(o.z));
    orr.w = __uint_as_float(f2tf32(o.w));
    *(float4*)&hr[(size_t)dd * 256 + c4 * 4] = orr;
}

// ---------------- GRU elementwise (float4, MUFU transcendentals) -------------
__global__ void gru_kernel(const float* __restrict__ grz, const float* __restrict__ gin,
                           const float* __restrict__ ghn, const float* __restrict__ h,
                           float* __restrict__ out) {
    int idx = blockIdx.x * 256 + threadIdx.x;
    int node = idx >> 6, c = idx & 63;
    float4 rr = *(const float4*)&grz[(size_t)node * 512 + c * 4];
    float4 zz = *(const float4*)&grz[(size_t)node * 512 + 256 + c * 4];
    float4 gn = *(const float4*)&gin[(size_t)idx * 4];
    float4 hn = *(const float4*)&ghn[(size_t)idx * 4];
    float4 hh = *(const float4*)&h[(size_t)idx * 4];
    float4 o;
    { float r = fsig(rr.x), z = fsig(zz.x);
      o.x = (1.f - z) * ftanh(gn.x + r * hn.x) + z * hh.x; }
    { float r = fsig(rr.y), z = fsig(zz.y);
      o.y = (1.f - z) * ftanh(gn.y + r * hn.y) + z * hh.y; }
    { float r = fsig(rr.z), z = fsig(zz.z);
      o.z = (1.f - z) * ftanh(gn.z + r * hn.z) + z * hh.z; }
    { float r = fsig(rr.w), z = fsig(zz.w);
      o.w = (1.f - z) * ftanh(gn.w + r * hn.w) + z * hh.w; }
    *(float4*)&out[(size_t)idx * 4] = o;
}

// ---------------- host launcher (fork-join over two streams) ----------------
extern "C" void kernel_launch(void* const* d_in, const int* in_sizes, int n_in,
                              void* d_out, int out_size) {
    const float* h_t      = (const float*)d_in[0];
    const float* h_prev   = (const float*)d_in[1];
    const float* W_intra  = (const float*)d_in[2];
    const float* b_intra  = (const float*)d_in[3];
    const float* a_intra  = (const float*)d_in[4];
    const float* ab_intra = (const float*)d_in[5];
    const float* W_cross  = (const float*)d_in[6];
    const float* a_cross  = (const float*)d_in[7];
    const float* W_ih     = (const float*)d_in[8];
    const float* W_hh     = (const float*)d_in[9];
    const float* b_ih     = (const float*)d_in[10];
    const float* b_hh     = (const float*)d_in[11];
    const int*   src_in   = (const int*)d_in[12];
    const int*   src_c    = (const int*)d_in[14];
    const int*   src_s    = (const int*)d_in[16];
    float* out = (float*)d_out;

    float *p_Wh, *p_x, *p_Whp, *p_h, *p_hr, *p_grz, *p_gin, *p_ghn;
    float *p_pki, *p_pkc, *p_pih, *p_phh, *p_vm, *p_es, *p_ed, *p_esP, *p_edX;
    cudaGetSymbolAddress((void**)&p_Wh,  d_Wh);
    cudaGetSymbolAddress((void**)&p_x,   d_x);
    cudaGetSymbolAddress((void**)&p_Whp, d_Whp);
    cudaGetSymbolAddress((void**)&p_h,   d_h);
    cudaGetSymbolAddress((void**)&p_hr,  d_hr);
    cudaGetSymbolAddress((void**)&p_grz, d_grz);
    cudaGetSymbolAddress((void**)&p_gin, d_gin);
    cudaGetSymbolAddress((void**)&p_ghn, d_ghn);
    cudaGetSymbolAddress((void**)&p_pki, d_pk_intra);
    cudaGetSymbolAddress((void**)&p_pkc, d_pk_cross);
    cudaGetSymbolAddress((void**)&p_pih, d_pih);
    cudaGetSymbolAddress((void**)&p_phh, d_phh);
    cudaGetSymbolAddress((void**)&p_vm,  d_vmat);
    cudaGetSymbolAddress((void**)&p_es,  d_es);
    cudaGetSymbolAddress((void**)&p_ed,  d_ed);
    cudaGetSymbolAddress((void**)&p_esP, d_esP);
    cudaGetSymbolAddress((void**)&p_edX, d_edX);

    cudaFuncSetAttribute(gemm_feat,  cudaFuncAttributeMaxDynamicSharedMemorySize, SMEMSZ);
    cudaFuncSetAttribute(gemm_gates, cudaFuncAttributeMaxDynamicSharedMemorySize, SMEMSZ);

    cudaStream_t s1;
    cudaStreamCreateWithFlags(&s1, cudaStreamNonBlocking);
    cudaEvent_t e0, e1, e2;
    cudaEventCreateWithFlags(&e0, cudaEventDisableTiming);
    cudaEventCreateWithFlags(&e1, cudaEventDisableTiming);
    cudaEventCreateWithFlags(&e2, cudaEventDisableTiming);

    dim3 gF((NN + BMM - 1) / BMM, 2);
    dim3 gG1((NN + BMM - 1) / BMM, 2);
    dim3 gG0((NN + BMM - 1) / BMM, 6);

    // s0: packs
    pack_all<<<2052, 256>>>(W_intra, W_cross, W_ih, W_hh, a_cross,
                            p_pki, p_pkc, p_pih, p_phh, p_vm);
    // fork s1 after packs
    cudaEventRecord(e0, 0);
    cudaStreamWaitEvent(s1, e0, 0);

    // s0: Wh branch (split) -> intra_agg ; s1: Whp branch (plain)
    gemm_feat<<<gF, 256, SMEMSZ>>>(h_t, h_prev, p_pki, p_pkc, b_intra,
                                   a_intra, a_cross, p_Wh, p_Whp,
                                   p_es, p_ed, p_esP, NN, 0);
    gemm_feat<<<gF, 256, SMEMSZ, s1>>>(h_t, h_prev, p_pki, p_pkc, b_intra,
                                       a_intra, a_cross, p_Wh, p_Whp,
                                       p_es, p_ed, p_esP, NN, 1);
    intra_agg<<<NN / 4, 256>>>(p_Wh, p_es, p_ed, ab_intra, src_in, p_vm, p_x, p_edX);

    // s1: cross_agg (needs edX from s0 + Whp/esP from s1)
    cudaEventRecord(e1, 0);
    cudaStreamWaitEvent(s1, e1, 0);
    cross_agg<<<NN / 4, 256, 0, s1>>>(p_Whp, p_esP, p_edX, src_c, src_s, p_h, p_hr);

    // s0 concurrently: gin GEMM (needs only x)
    gemm_gates<<<gG1, 256, SMEMSZ>>>(p_x, p_hr, p_pih, p_phh, b_ih, b_hh,
                                     p_grz, p_gin, p_ghn, NN, 1);

    // join s1 -> s0, then grz+ghn and gru
    cudaEventRecord(e2, s1);
    cudaStreamWaitEvent(0, e2, 0);
    gemm_gates<<<gG0, 256, SMEMSZ>>>(p_x, p_hr, p_pih, p_phh, b_ih, b_hh,
                                     p_grz, p_gin, p_ghn, NN, 0);
    gru_kernel<<<NN / 4, 256>>>(p_grz, p_gin, p_ghn, p_h, out);

    cudaEventDestroy(e0);
    cudaEventDestroy(e1);
    cudaEventDestroy(e2);
    cudaStreamDestroy(s1);
}